// round 1
// baseline (speedup 1.0000x reference)
#include <cuda_runtime.h>
#include <math.h>

#define BB 4
#define TT 2048
#define CC 1024
#define HH 16
#define DD 64
#define BT (BB*TT)   // 8192

// Scratch (device globals: allocation-free per harness rules)
__device__ float g_q[(size_t)BB*HH*TT*DD];   // [B,H,T,D] 32MB
__device__ float g_k[(size_t)BB*HH*TT*DD];
__device__ float g_v[(size_t)BB*HH*TT*DD];
__device__ float g_y[(size_t)BT*CC];         // attention out, concat layout [B,T,H*D]

// ---------------------------------------------------------------------------
// Kernel 1: QKV projection.  q[b,h,t,d] = sum_c x[b,t,c] * W[h,c,d]
// grid (BT/64, H, 3), block 256.  64x64 output tile, 4x4 per thread, k-chunk 32.
// ---------------------------------------------------------------------------
__global__ __launch_bounds__(256) void qkv_kernel(
    const float* __restrict__ x, const float* __restrict__ Wq,
    const float* __restrict__ Wk, const float* __restrict__ Wv)
{
    __shared__ float Xs[32][68];   // [kk][row], padded
    __shared__ float Ws[32][68];   // [kk][d]

    const int m0 = blockIdx.x * 64;
    const int h  = blockIdx.y;
    const int z  = blockIdx.z;
    const float* W = (z == 0 ? Wq : (z == 1 ? Wk : Wv)) + (size_t)h * CC * DD;
    float* outb    = (z == 0 ? g_q : (z == 1 ? g_k : g_v));

    const int b  = m0 / TT;
    const int t0 = m0 % TT;
    float* obase = outb + ((size_t)(b * HH + h) * TT + t0) * DD;

    const int tid = threadIdx.x;
    const int tx = tid & 15, ty = tid >> 4;

    float acc[4][4] = {};

    for (int k0 = 0; k0 < CC; k0 += 32) {
        #pragma unroll
        for (int l = 0; l < 2; l++) {
            int idx = tid + l * 256;
            // X tile: 64 rows x 32 k  (transposed store)
            int r  = idx >> 3, c4 = (idx & 7) << 2;
            float4 xv = *(const float4*)&x[(size_t)(m0 + r) * CC + k0 + c4];
            Xs[c4 + 0][r] = xv.x; Xs[c4 + 1][r] = xv.y;
            Xs[c4 + 2][r] = xv.z; Xs[c4 + 3][r] = xv.w;
            // W tile: 32 k x 64 d (direct)
            int kk = idx >> 4, d4 = (idx & 15) << 2;
            *(float4*)&Ws[kk][d4] = *(const float4*)&W[(size_t)(k0 + kk) * DD + d4];
        }
        __syncthreads();
        #pragma unroll
        for (int kk = 0; kk < 32; kk++) {
            float4 av = *(float4*)&Xs[kk][ty * 4];
            float4 wv = *(float4*)&Ws[kk][tx * 4];
            float aa[4] = {av.x, av.y, av.z, av.w};
            float ww[4] = {wv.x, wv.y, wv.z, wv.w};
            #pragma unroll
            for (int i = 0; i < 4; i++)
                #pragma unroll
                for (int j = 0; j < 4; j++)
                    acc[i][j] += aa[i] * ww[j];
        }
        __syncthreads();
    }
    #pragma unroll
    for (int i = 0; i < 4; i++) {
        float4 o4 = make_float4(acc[i][0], acc[i][1], acc[i][2], acc[i][3]);
        *(float4*)&obase[(size_t)(ty * 4 + i) * DD + tx * 4] = o4;
    }
}

// ---------------------------------------------------------------------------
// Kernel 2: causal flash attention, fp32 online softmax.
// grid (T/64, H, B), block 256.  q-tile = 64 rows; loop k-tiles 0..qt.
// Thread mapping: row r = tid>>2; lane-within-row a = tid&3.
// S phase : thread owns cols c = 4*cc + a (cc 0..15)
// PV phase: thread owns d    = 4*a + 16*dd + j (dd 0..3, j 0..3)
// ---------------------------------------------------------------------------
__global__ __launch_bounds__(256) void attn_kernel()
{
    extern __shared__ float sm[];
    float* Qs = sm;                 // [64][68]
    float* Ks = sm + 64 * 68;
    float* Vs = sm + 2 * 64 * 68;
    float* Ps = sm + 3 * 64 * 68;

    const int qt = blockIdx.x, h = blockIdx.y, b = blockIdx.z;
    const int tid = threadIdx.x;
    const int r = tid >> 2;
    const int a = tid & 3;
    const float scale = 0.03125f;   // C^-0.5 = 1024^-0.5 (reference scales by n_embd!)

    const float* qb  = g_q + ((size_t)(b * HH + h) * TT + qt * 64) * DD;
    const float* kb0 = g_k + ((size_t)(b * HH + h) * TT) * DD;
    const float* vb0 = g_v + ((size_t)(b * HH + h) * TT) * DD;

    // Load Q tile (pre-scaled)
    #pragma unroll
    for (int l = 0; l < 4; l++) {
        int idx = tid + l * 256;
        int rr = idx >> 4, d4 = (idx & 15) << 2;
        float4 q4 = *(const float4*)&qb[(size_t)rr * DD + d4];
        q4.x *= scale; q4.y *= scale; q4.z *= scale; q4.w *= scale;
        *(float4*)&Qs[rr * 68 + d4] = q4;
    }

    float m = -1e30f, lsum = 0.f;
    float o[4][4] = {};

    for (int kt = 0; kt <= qt; kt++) {
        const float* kb = kb0 + (size_t)kt * 64 * DD;
        const float* vb = vb0 + (size_t)kt * 64 * DD;
        #pragma unroll
        for (int l = 0; l < 4; l++) {
            int idx = tid + l * 256;
            int rr = idx >> 4, d4 = (idx & 15) << 2;
            *(float4*)&Ks[rr * 68 + d4] = *(const float4*)&kb[(size_t)rr * DD + d4];
            *(float4*)&Vs[rr * 68 + d4] = *(const float4*)&vb[(size_t)rr * DD + d4];
        }
        __syncthreads();

        // ---- S = Q K^T ----
        float sv[16];
        #pragma unroll
        for (int cc = 0; cc < 16; cc++) sv[cc] = 0.f;
        #pragma unroll 4
        for (int d4 = 0; d4 < 64; d4 += 4) {
            float4 q4 = *(float4*)&Qs[r * 68 + d4];
            #pragma unroll
            for (int cc = 0; cc < 16; cc++) {
                int c = cc * 4 + a;
                float4 k4 = *(float4*)&Ks[c * 68 + d4];
                sv[cc] += q4.x * k4.x + q4.y * k4.y + q4.z * k4.z + q4.w * k4.w;
            }
        }
        if (kt == qt) {
            #pragma unroll
            for (int cc = 0; cc < 16; cc++) {
                int c = cc * 4 + a;
                if (c > r) sv[cc] = -1e30f;
            }
        }

        // ---- online softmax ----
        float mloc = sv[0];
        #pragma unroll
        for (int cc = 1; cc < 16; cc++) mloc = fmaxf(mloc, sv[cc]);
        mloc = fmaxf(mloc, __shfl_xor_sync(0xffffffffu, mloc, 1));
        mloc = fmaxf(mloc, __shfl_xor_sync(0xffffffffu, mloc, 2));
        float mnew = fmaxf(m, mloc);
        float corr = __expf(m - mnew);
        float ps = 0.f;
        #pragma unroll
        for (int cc = 0; cc < 16; cc++) {
            float p = __expf(sv[cc] - mnew);
            ps += p;
            Ps[r * 68 + cc * 4 + a] = p;
        }
        ps += __shfl_xor_sync(0xffffffffu, ps, 1);
        ps += __shfl_xor_sync(0xffffffffu, ps, 2);
        lsum = lsum * corr + ps;
        m = mnew;
        #pragma unroll
        for (int dd = 0; dd < 4; dd++)
            #pragma unroll
            for (int j = 0; j < 4; j++) o[dd][j] *= corr;
        __syncthreads();

        // ---- O += P V ----
        const int dbase = a * 4;
        #pragma unroll 4
        for (int s4 = 0; s4 < 16; s4++) {
            float4 p4 = *(float4*)&Ps[r * 68 + s4 * 4];
            float pj[4] = {p4.x, p4.y, p4.z, p4.w};
            #pragma unroll
            for (int js = 0; js < 4; js++) {
                int s = s4 * 4 + js;
                #pragma unroll
                for (int dd = 0; dd < 4; dd++) {
                    float4 v4 = *(float4*)&Vs[s * 68 + dbase + dd * 16];
                    o[dd][0] += pj[js] * v4.x;
                    o[dd][1] += pj[js] * v4.y;
                    o[dd][2] += pj[js] * v4.z;
                    o[dd][3] += pj[js] * v4.w;
                }
            }
        }
        __syncthreads();
    }

    // ---- normalize and write in concat layout [B,T,H*D] ----
    const float inv = 1.0f / lsum;
    const int tg = qt * 64 + r;
    float* yb = g_y + (size_t)(b * TT + tg) * CC + h * DD;
    #pragma unroll
    for (int dd = 0; dd < 4; dd++) {
        float4 o4 = make_float4(o[dd][0] * inv, o[dd][1] * inv,
                                o[dd][2] * inv, o[dd][3] * inv);
        *(float4*)&yb[a * 4 + dd * 16] = o4;
    }
}

// ---------------------------------------------------------------------------
// Kernel 3: output projection.  out[m,n] = sum_c y[m,c]*Wproj[n,c] + b[n]
// grid (BT/64, C/64), block 256. Same tiling as kernel 1; W loaded transposed.
// ---------------------------------------------------------------------------
__global__ __launch_bounds__(256) void proj_kernel(
    const float* __restrict__ Wp, const float* __restrict__ bp,
    float* __restrict__ out)
{
    __shared__ float Ys[32][68];   // [kk][row]
    __shared__ float Ws[32][68];   // [kk][n]

    const int m0 = blockIdx.x * 64;
    const int n0 = blockIdx.y * 64;
    const int tid = threadIdx.x;
    const int tx = tid & 15, ty = tid >> 4;

    float acc[4][4] = {};

    for (int k0 = 0; k0 < CC; k0 += 32) {
        #pragma unroll
        for (int l = 0; l < 2; l++) {
            int idx = tid + l * 256;
            int r  = idx >> 3, c4 = (idx & 7) << 2;
            float4 yv = *(const float4*)&g_y[(size_t)(m0 + r) * CC + k0 + c4];
            Ys[c4 + 0][r] = yv.x; Ys[c4 + 1][r] = yv.y;
            Ys[c4 + 2][r] = yv.z; Ys[c4 + 3][r] = yv.w;
            float4 wv = *(const float4*)&Wp[(size_t)(n0 + r) * CC + k0 + c4];
            Ws[c4 + 0][r] = wv.x; Ws[c4 + 1][r] = wv.y;
            Ws[c4 + 2][r] = wv.z; Ws[c4 + 3][r] = wv.w;
        }
        __syncthreads();
        #pragma unroll
        for (int kk = 0; kk < 32; kk++) {
            float4 av = *(float4*)&Ys[kk][ty * 4];
            float4 wv = *(float4*)&Ws[kk][tx * 4];
            float aa[4] = {av.x, av.y, av.z, av.w};
            float ww[4] = {wv.x, wv.y, wv.z, wv.w};
            #pragma unroll
            for (int i = 0; i < 4; i++)
                #pragma unroll
                for (int j = 0; j < 4; j++)
                    acc[i][j] += aa[i] * ww[j];
        }
        __syncthreads();
    }

    float4 b4 = *(const float4*)&bp[n0 + tx * 4];
    float bb[4] = {b4.x, b4.y, b4.z, b4.w};
    #pragma unroll
    for (int i = 0; i < 4; i++) {
        float4 o4 = make_float4(acc[i][0] + bb[0], acc[i][1] + bb[1],
                                acc[i][2] + bb[2], acc[i][3] + bb[3]);
        *(float4*)&out[(size_t)(m0 + ty * 4 + i) * CC + n0 + tx * 4] = o4;
    }
}

// ---------------------------------------------------------------------------
extern "C" void kernel_launch(void* const* d_in, const int* in_sizes, int n_in,
                              void* d_out, int out_size)
{
    (void)in_sizes; (void)n_in; (void)out_size;
    const float* x  = (const float*)d_in[0];
    const float* Wq = (const float*)d_in[1];
    const float* Wk = (const float*)d_in[2];
    const float* Wv = (const float*)d_in[3];
    const float* Wp = (const float*)d_in[4];
    const float* bp = (const float*)d_in[5];
    float* out = (float*)d_out;

    const int attn_smem = 4 * 64 * 68 * (int)sizeof(float);   // 69,632 B
    cudaFuncSetAttribute(attn_kernel,
                         cudaFuncAttributeMaxDynamicSharedMemorySize, attn_smem);

    qkv_kernel<<<dim3(BT / 64, HH, 3), 256>>>(x, Wq, Wk, Wv);
    attn_kernel<<<dim3(TT / 64, HH, BB), 256, attn_smem>>>();
    proj_kernel<<<dim3(BT / 64, CC / 64), 256>>>(Wp, bp, out);
}

// round 4
// speedup vs baseline: 1.5191x; 1.5191x over previous
#include <cuda_runtime.h>
#include <math.h>
#include <stdint.h>

#define BB 4
#define TT 2048
#define CC 1024
#define HH 16
#define DD 64
#define BT (BB*TT)   // 8192

// ---------------- scratch (device globals; allocation-free) ----------------
__device__ float g_q [(size_t)BB*HH*TT*DD];   // [B,H,T,D]
__device__ float g_k [(size_t)BB*HH*TT*DD];
__device__ float g_v [(size_t)BB*HH*TT*DD];
__device__ float g_y [(size_t)BT*CC];         // attn out [B,T,H*D], tf32-rounded
__device__ float g_xr[(size_t)BT*CC];         // x rounded to tf32
__device__ float g_wt[(size_t)3*CC*CC];       // W transposed [z*1024+h*64+d][c], tf32
__device__ float g_wpr[(size_t)CC*CC];        // Wproj rounded [n][c]

// ---------------- helpers ----------------
__device__ __forceinline__ float rntf32(float v) {
    uint32_t r;
    asm("cvt.rna.tf32.f32 %0, %1;" : "=r"(r) : "f"(v));   // tf32 dest is .b32
    return __uint_as_float(r);
}
__device__ __forceinline__ uint32_t smem_u32(const void* p) {
    uint32_t a;
    asm("{ .reg .u64 t; cvta.to.shared.u64 t, %1; cvt.u32.u64 %0, t; }" : "=r"(a) : "l"(p));
    return a;
}
__device__ __forceinline__ void cpa16(uint32_t dst, const void* src) {
    asm volatile("cp.async.cg.shared.global [%0], [%1], 16;" :: "r"(dst), "l"(src));
}
__device__ __forceinline__ void cpa_commit() {
    asm volatile("cp.async.commit_group;" ::: "memory");
}
__device__ __forceinline__ void cpa_wait1() {
    asm volatile("cp.async.wait_group 1;" ::: "memory");
}
__device__ __forceinline__ void mma_tf32(float c[4], const uint32_t a[4],
                                         const uint32_t b[2]) {
    asm volatile(
        "mma.sync.aligned.m16n8k8.row.col.f32.tf32.tf32.f32 "
        "{%0,%1,%2,%3}, {%4,%5,%6,%7}, {%8,%9}, {%0,%1,%2,%3};"
        : "+f"(c[0]), "+f"(c[1]), "+f"(c[2]), "+f"(c[3])
        : "r"(a[0]), "r"(a[1]), "r"(a[2]), "r"(a[3]), "r"(b[0]), "r"(b[1]));
}

// ---------------------------------------------------------------------------
// Prep: tf32-round a flat array.  which==0 -> g_xr, which==1 -> g_wpr
// ---------------------------------------------------------------------------
__global__ __launch_bounds__(256) void round_kernel(const float* __restrict__ src,
                                                    int which, int n4)
{
    int i = blockIdx.x * blockDim.x + threadIdx.x;
    if (i >= n4) return;
    float* dst = which ? g_wpr : g_xr;
    float4 v = *(const float4*)(src + (size_t)i * 4);
    v.x = rntf32(v.x); v.y = rntf32(v.y); v.z = rntf32(v.z); v.w = rntf32(v.w);
    *(float4*)(dst + (size_t)i * 4) = v;
}

// ---------------------------------------------------------------------------
// Prep: transpose W[z][h][c][d] -> g_wt[(z*1024+h*64+d)][c], tf32-rounded.
// grid (32, 2, 48) block (32, 8)
// ---------------------------------------------------------------------------
__global__ __launch_bounds__(256) void transpose_w(
    const float* __restrict__ Wq, const float* __restrict__ Wk,
    const float* __restrict__ Wv)
{
    __shared__ float tile[32][33];
    const int zh = blockIdx.z;
    const int z = zh >> 4, h = zh & 15;
    const float* W = (z == 0 ? Wq : (z == 1 ? Wk : Wv)) + (size_t)h * CC * DD;
    const int c0 = blockIdx.x * 32, d0 = blockIdx.y * 32;
    const int tx = threadIdx.x, ty = threadIdx.y;

    #pragma unroll
    for (int i = 0; i < 4; i++) {
        int c = c0 + ty + i * 8;
        tile[ty + i * 8][tx] = rntf32(W[(size_t)c * DD + d0 + tx]);
    }
    __syncthreads();
    const size_t base_n = (size_t)zh * 64;
    #pragma unroll
    for (int i = 0; i < 4; i++) {
        int d = d0 + ty + i * 8;
        g_wt[(base_n + d) * CC + c0 + tx] = tile[tx][ty + i * 8];
    }
}

// ---------------------------------------------------------------------------
// mma.sync tf32 GEMM: D[128x128 tile] = A[128,1024] * B[128,1024]^T
// MODE 0: QKV (A=g_xr, B=g_wt z-slab; scatter epilogue to g_q/k/v)
// MODE 1: proj (A=g_y,  B=g_wpr; +bias, writes d_out)
// 256 threads = 8 warps (2 m x 4 n), warp tile 64x32, k-chunk 32, 2-stage cp.async.
// Smem stage: A[128][36] + B[128][36] floats (pad 36 -> conflict-free scalar LDS).
// ---------------------------------------------------------------------------
#define SROW 36
#define STAGE_FLOATS (2 * 128 * SROW)          // A + B per stage = 9216
#define GEMM_SMEM (2 * STAGE_FLOATS * 4)       // 73728 bytes

template <int MODE>
__global__ __launch_bounds__(256) void gemm_kernel(
    const float* __restrict__ bias, float* __restrict__ out)
{
    extern __shared__ __align__(16) float sm[];
    const uint32_t sbase = smem_u32(sm);

    const int tid = threadIdx.x;
    const int lane = tid & 31, wid = tid >> 5;
    const int wm = wid >> 2;          // 0..1
    const int wn = wid & 3;           // 0..3
    const int m0 = blockIdx.x * 128;
    const int n0 = blockIdx.y * 128;

    const float* A  = (MODE == 0) ? g_xr : g_y;
    const float* Bw = (MODE == 0) ? (g_wt + (size_t)blockIdx.z * CC * CC) : g_wpr;

    // loader: chunk c (k0=c*32) into stage s
    auto load_chunk = [&](int c, int s) {
        const int k0 = c * 32;
        const uint32_t abase = sbase + (uint32_t)s * STAGE_FLOATS * 4;
        const uint32_t bbase = abase + 128 * SROW * 4;
        #pragma unroll
        for (int i = 0; i < 4; i++) {
            int idx = tid + i * 256;              // 0..1023
            int row = idx >> 3, seg = idx & 7;
            uint32_t off = (uint32_t)(row * SROW + seg * 4) * 4;
            cpa16(abase + off, A  + (size_t)(m0 + row) * CC + k0 + seg * 4);
            cpa16(bbase + off, Bw + (size_t)(n0 + row) * CC + k0 + seg * 4);
        }
    };

    load_chunk(0, 0); cpa_commit();
    load_chunk(1, 1); cpa_commit();

    float acc[4][4][4] = {};          // [mt][nt][frag]

    const int NC = CC / 32;           // 32 chunks
    for (int c = 0; c < NC; c++) {
        cpa_wait1();
        __syncthreads();
        const float* Abase = sm + (c & 1) * STAGE_FLOATS;
        const float* Bbase = Abase + 128 * SROW;

        #pragma unroll
        for (int ks = 0; ks < 4; ks++) {
            const int k = ks * 8 + (lane & 3);
            uint32_t a[4][4], b[4][2];
            #pragma unroll
            for (int mt = 0; mt < 4; mt++) {
                const int m = wm * 64 + mt * 16 + (lane >> 2);
                a[mt][0] = __float_as_uint(Abase[m * SROW + k]);
                a[mt][1] = __float_as_uint(Abase[(m + 8) * SROW + k]);
                a[mt][2] = __float_as_uint(Abase[m * SROW + k + 4]);
                a[mt][3] = __float_as_uint(Abase[(m + 8) * SROW + k + 4]);
            }
            #pragma unroll
            for (int nt = 0; nt < 4; nt++) {
                const int n = wn * 32 + nt * 8 + (lane >> 2);
                b[nt][0] = __float_as_uint(Bbase[n * SROW + k]);
                b[nt][1] = __float_as_uint(Bbase[n * SROW + k + 4]);
            }
            #pragma unroll
            for (int mt = 0; mt < 4; mt++)
                #pragma unroll
                for (int nt = 0; nt < 4; nt++)
                    mma_tf32(acc[mt][nt], a[mt], b[nt]);
        }
        __syncthreads();
        if (c + 2 < NC) load_chunk(c + 2, c & 1);
        cpa_commit();
    }

    // ---- epilogue ----
    #pragma unroll
    for (int mt = 0; mt < 4; mt++) {
        const int m = m0 + wm * 64 + mt * 16 + (lane >> 2);
        #pragma unroll
        for (int nt = 0; nt < 4; nt++) {
            const int n = n0 + wn * 32 + nt * 8 + 2 * (lane & 3);
            if (MODE == 0) {
                const int z = blockIdx.z;
                float* outb = (z == 0 ? g_q : (z == 1 ? g_k : g_v));
                const int h = n >> 6, d = n & 63;
                #pragma unroll
                for (int half = 0; half < 2; half++) {
                    const int mm = m + half * 8;
                    const int bb = mm >> 11, t = mm & 2047;
                    float2 o2 = make_float2(acc[mt][nt][half * 2],
                                            acc[mt][nt][half * 2 + 1]);
                    *(float2*)(outb + (((size_t)(bb * HH + h) * TT + t) * DD + d)) = o2;
                }
            } else {
                const float2 b2 = *(const float2*)(bias + n);
                #pragma unroll
                for (int half = 0; half < 2; half++) {
                    const int mm = m + half * 8;
                    float2 o2 = make_float2(acc[mt][nt][half * 2] + b2.x,
                                            acc[mt][nt][half * 2 + 1] + b2.y);
                    *(float2*)(out + (size_t)mm * CC + n) = o2;
                }
            }
        }
    }
}

// ---------------------------------------------------------------------------
// Causal flash attention, fp32 online softmax (unchanged; epilogue stores
// tf32-rounded values which feed the proj GEMM's A operand).
// ---------------------------------------------------------------------------
__global__ __launch_bounds__(256) void attn_kernel()
{
    extern __shared__ float smf[];
    float* Qs = smf;                 // [64][68]
    float* Ks = smf + 64 * 68;
    float* Vs = smf + 2 * 64 * 68;
    float* Ps = smf + 3 * 64 * 68;

    const int qt = blockIdx.x, h = blockIdx.y, b = blockIdx.z;
    const int tid = threadIdx.x;
    const int r = tid >> 2;
    const int a = tid & 3;
    const float scale = 0.03125f;   // C^-0.5 = 1024^-0.5

    const float* qb  = g_q + ((size_t)(b * HH + h) * TT + qt * 64) * DD;
    const float* kb0 = g_k + ((size_t)(b * HH + h) * TT) * DD;
    const float* vb0 = g_v + ((size_t)(b * HH + h) * TT) * DD;

    #pragma unroll
    for (int l = 0; l < 4; l++) {
        int idx = tid + l * 256;
        int rr = idx >> 4, d4 = (idx & 15) << 2;
        float4 q4 = *(const float4*)&qb[(size_t)rr * DD + d4];
        q4.x *= scale; q4.y *= scale; q4.z *= scale; q4.w *= scale;
        *(float4*)&Qs[rr * 68 + d4] = q4;
    }

    float m = -1e30f, lsum = 0.f;
    float o[4][4] = {};

    for (int kt = 0; kt <= qt; kt++) {
        const float* kb = kb0 + (size_t)kt * 64 * DD;
        const float* vb = vb0 + (size_t)kt * 64 * DD;
        #pragma unroll
        for (int l = 0; l < 4; l++) {
            int idx = tid + l * 256;
            int rr = idx >> 4, d4 = (idx & 15) << 2;
            *(float4*)&Ks[rr * 68 + d4] = *(const float4*)&kb[(size_t)rr * DD + d4];
            *(float4*)&Vs[rr * 68 + d4] = *(const float4*)&vb[(size_t)rr * DD + d4];
        }
        __syncthreads();

        float sv[16];
        #pragma unroll
        for (int cc = 0; cc < 16; cc++) sv[cc] = 0.f;
        #pragma unroll 4
        for (int d4 = 0; d4 < 64; d4 += 4) {
            float4 q4 = *(float4*)&Qs[r * 68 + d4];
            #pragma unroll
            for (int cc = 0; cc < 16; cc++) {
                int c = cc * 4 + a;
                float4 k4 = *(float4*)&Ks[c * 68 + d4];
                sv[cc] += q4.x * k4.x + q4.y * k4.y + q4.z * k4.z + q4.w * k4.w;
            }
        }
        if (kt == qt) {
            #pragma unroll
            for (int cc = 0; cc < 16; cc++) {
                int c = cc * 4 + a;
                if (c > r) sv[cc] = -1e30f;
            }
        }

        float mloc = sv[0];
        #pragma unroll
        for (int cc = 1; cc < 16; cc++) mloc = fmaxf(mloc, sv[cc]);
        mloc = fmaxf(mloc, __shfl_xor_sync(0xffffffffu, mloc, 1));
        mloc = fmaxf(mloc, __shfl_xor_sync(0xffffffffu, mloc, 2));
        float mnew = fmaxf(m, mloc);
        float corr = __expf(m - mnew);
        float ps = 0.f;
        #pragma unroll
        for (int cc = 0; cc < 16; cc++) {
            float p = __expf(sv[cc] - mnew);
            ps += p;
            Ps[r * 68 + cc * 4 + a] = p;
        }
        ps += __shfl_xor_sync(0xffffffffu, ps, 1);
        ps += __shfl_xor_sync(0xffffffffu, ps, 2);
        lsum = lsum * corr + ps;
        m = mnew;
        #pragma unroll
        for (int dd = 0; dd < 4; dd++)
            #pragma unroll
            for (int j = 0; j < 4; j++) o[dd][j] *= corr;
        __syncthreads();

        const int dbase = a * 4;
        #pragma unroll 4
        for (int s4 = 0; s4 < 16; s4++) {
            float4 p4 = *(float4*)&Ps[r * 68 + s4 * 4];
            float pj[4] = {p4.x, p4.y, p4.z, p4.w};
            #pragma unroll
            for (int js = 0; js < 4; js++) {
                int s = s4 * 4 + js;
                #pragma unroll
                for (int dd = 0; dd < 4; dd++) {
                    float4 v4 = *(float4*)&Vs[s * 68 + dbase + dd * 16];
                    o[dd][0] += pj[js] * v4.x;
                    o[dd][1] += pj[js] * v4.y;
                    o[dd][2] += pj[js] * v4.z;
                    o[dd][3] += pj[js] * v4.w;
                }
            }
        }
        __syncthreads();
    }

    const float inv = 1.0f / lsum;
    const int tg = qt * 64 + r;
    float* yb = g_y + (size_t)(b * TT + tg) * CC + h * DD;
    #pragma unroll
    for (int dd = 0; dd < 4; dd++) {
        float4 o4 = make_float4(rntf32(o[dd][0] * inv), rntf32(o[dd][1] * inv),
                                rntf32(o[dd][2] * inv), rntf32(o[dd][3] * inv));
        *(float4*)&yb[a * 4 + dd * 16] = o4;
    }
}

// ---------------------------------------------------------------------------
extern "C" void kernel_launch(void* const* d_in, const int* in_sizes, int n_in,
                              void* d_out, int out_size)
{
    (void)in_sizes; (void)n_in; (void)out_size;
    const float* x  = (const float*)d_in[0];
    const float* Wq = (const float*)d_in[1];
    const float* Wk = (const float*)d_in[2];
    const float* Wv = (const float*)d_in[3];
    const float* Wp = (const float*)d_in[4];
    const float* bp = (const float*)d_in[5];
    float* out = (float*)d_out;

    const int attn_smem = 4 * 64 * 68 * (int)sizeof(float);
    cudaFuncSetAttribute(attn_kernel,
                         cudaFuncAttributeMaxDynamicSharedMemorySize, attn_smem);
    cudaFuncSetAttribute(gemm_kernel<0>,
                         cudaFuncAttributeMaxDynamicSharedMemorySize, GEMM_SMEM);
    cudaFuncSetAttribute(gemm_kernel<1>,
                         cudaFuncAttributeMaxDynamicSharedMemorySize, GEMM_SMEM);

    // prep: tf32-round x and Wproj, transpose+round QKV weights
    round_kernel<<<(BT * CC / 4 + 255) / 256, 256>>>(x, 0, BT * CC / 4);
    round_kernel<<<(CC * CC / 4 + 255) / 256, 256>>>(Wp, 1, CC * CC / 4);
    transpose_w<<<dim3(32, 2, 48), dim3(32, 8)>>>(Wq, Wk, Wv);

    // QKV projections (tensor cores, tf32 mma.sync)
    gemm_kernel<0><<<dim3(BT / 128, CC / 128, 3), 256, GEMM_SMEM>>>(nullptr, nullptr);

    // attention (SIMT fp32, unchanged)
    attn_kernel<<<dim3(TT / 64, HH, BB), 256, attn_smem>>>();

    // output projection + bias (tensor cores)
    gemm_kernel<1><<<dim3(BT / 128, CC / 128, 1), 256, GEMM_SMEM>>>(bp, out);
}

// round 5
// speedup vs baseline: 4.7368x; 3.1182x over previous
#include <cuda_runtime.h>
#include <math.h>
#include <stdint.h>

#define BB 4
#define TT 2048
#define CC 1024
#define HH 16
#define DD 64
#define BT (BB*TT)   // 8192

// ---------------- scratch (device globals; allocation-free) ----------------
__device__ float g_q [(size_t)BB*HH*TT*DD];   // [B,H,T,D], tf32-rounded
__device__ float g_k [(size_t)BB*HH*TT*DD];   // tf32-rounded
__device__ float g_v [(size_t)BB*HH*TT*DD];   // tf32-rounded
__device__ float g_y [(size_t)BT*CC];         // attn out [B,T,H*D], tf32-rounded
__device__ float g_xr[(size_t)BT*CC];         // x rounded to tf32
__device__ float g_wt[(size_t)3*CC*CC];       // W transposed [z*1024+h*64+d][c], tf32
__device__ float g_wpr[(size_t)CC*CC];        // Wproj rounded [n][c]

// ---------------- helpers ----------------
__device__ __forceinline__ float rntf32(float v) {
    uint32_t r;
    asm("cvt.rna.tf32.f32 %0, %1;" : "=r"(r) : "f"(v));
    return __uint_as_float(r);
}
__device__ __forceinline__ uint32_t smem_u32(const void* p) {
    uint32_t a;
    asm("{ .reg .u64 t; cvta.to.shared.u64 t, %1; cvt.u32.u64 %0, t; }" : "=r"(a) : "l"(p));
    return a;
}
__device__ __forceinline__ void cpa16(uint32_t dst, const void* src) {
    asm volatile("cp.async.cg.shared.global [%0], [%1], 16;" :: "r"(dst), "l"(src));
}
__device__ __forceinline__ void cpa_commit() {
    asm volatile("cp.async.commit_group;" ::: "memory");
}
__device__ __forceinline__ void cpa_wait1() {
    asm volatile("cp.async.wait_group 1;" ::: "memory");
}
__device__ __forceinline__ void cpa_wait0() {
    asm volatile("cp.async.wait_group 0;" ::: "memory");
}
__device__ __forceinline__ void mma_tf32(float c[4], const uint32_t a[4],
                                         const uint32_t b[2]) {
    asm volatile(
        "mma.sync.aligned.m16n8k8.row.col.f32.tf32.tf32.f32 "
        "{%0,%1,%2,%3}, {%4,%5,%6,%7}, {%8,%9}, {%0,%1,%2,%3};"
        : "+f"(c[0]), "+f"(c[1]), "+f"(c[2]), "+f"(c[3])
        : "r"(a[0]), "r"(a[1]), "r"(a[2]), "r"(a[3]), "r"(b[0]), "r"(b[1]));
}

// ---------------------------------------------------------------------------
// Prep: tf32-round a flat array.  which==0 -> g_xr, which==1 -> g_wpr
// ---------------------------------------------------------------------------
__global__ __launch_bounds__(256) void round_kernel(const float* __restrict__ src,
                                                    int which, int n4)
{
    int i = blockIdx.x * blockDim.x + threadIdx.x;
    if (i >= n4) return;
    float* dst = which ? g_wpr : g_xr;
    float4 v = *(const float4*)(src + (size_t)i * 4);
    v.x = rntf32(v.x); v.y = rntf32(v.y); v.z = rntf32(v.z); v.w = rntf32(v.w);
    *(float4*)(dst + (size_t)i * 4) = v;
}

// ---------------------------------------------------------------------------
// Prep: transpose W[z][h][c][d] -> g_wt[(z*1024+h*64+d)][c], tf32-rounded.
// ---------------------------------------------------------------------------
__global__ __launch_bounds__(256) void transpose_w(
    const float* __restrict__ Wq, const float* __restrict__ Wk,
    const float* __restrict__ Wv)
{
    __shared__ float tile[32][33];
    const int zh = blockIdx.z;
    const int z = zh >> 4, h = zh & 15;
    const float* W = (z == 0 ? Wq : (z == 1 ? Wk : Wv)) + (size_t)h * CC * DD;
    const int c0 = blockIdx.x * 32, d0 = blockIdx.y * 32;
    const int tx = threadIdx.x, ty = threadIdx.y;

    #pragma unroll
    for (int i = 0; i < 4; i++) {
        int c = c0 + ty + i * 8;
        tile[ty + i * 8][tx] = rntf32(W[(size_t)c * DD + d0 + tx]);
    }
    __syncthreads();
    const size_t base_n = (size_t)zh * 64;
    #pragma unroll
    for (int i = 0; i < 4; i++) {
        int d = d0 + ty + i * 8;
        g_wt[(base_n + d) * CC + c0 + tx] = tile[tx][ty + i * 8];
    }
}

// ---------------------------------------------------------------------------
// mma.sync tf32 GEMM (unchanged structure; MODE 0 epilogue now tf32-rounds).
// ---------------------------------------------------------------------------
#define SROW 36
#define STAGE_FLOATS (2 * 128 * SROW)
#define GEMM_SMEM (2 * STAGE_FLOATS * 4)

template <int MODE>
__global__ __launch_bounds__(256) void gemm_kernel(
    const float* __restrict__ bias, float* __restrict__ out)
{
    extern __shared__ __align__(16) float sm[];
    const uint32_t sbase = smem_u32(sm);

    const int tid = threadIdx.x;
    const int lane = tid & 31, wid = tid >> 5;
    const int wm = wid >> 2;
    const int wn = wid & 3;
    const int m0 = blockIdx.x * 128;
    const int n0 = blockIdx.y * 128;

    const float* A  = (MODE == 0) ? g_xr : g_y;
    const float* Bw = (MODE == 0) ? (g_wt + (size_t)blockIdx.z * CC * CC) : g_wpr;

    auto load_chunk = [&](int c, int s) {
        const int k0 = c * 32;
        const uint32_t abase = sbase + (uint32_t)s * STAGE_FLOATS * 4;
        const uint32_t bbase = abase + 128 * SROW * 4;
        #pragma unroll
        for (int i = 0; i < 4; i++) {
            int idx = tid + i * 256;
            int row = idx >> 3, seg = idx & 7;
            uint32_t off = (uint32_t)(row * SROW + seg * 4) * 4;
            cpa16(abase + off, A  + (size_t)(m0 + row) * CC + k0 + seg * 4);
            cpa16(bbase + off, Bw + (size_t)(n0 + row) * CC + k0 + seg * 4);
        }
    };

    load_chunk(0, 0); cpa_commit();
    load_chunk(1, 1); cpa_commit();

    float acc[4][4][4] = {};

    const int NC = CC / 32;
    for (int c = 0; c < NC; c++) {
        cpa_wait1();
        __syncthreads();
        const float* Abase = sm + (c & 1) * STAGE_FLOATS;
        const float* Bbase = Abase + 128 * SROW;

        #pragma unroll
        for (int ks = 0; ks < 4; ks++) {
            const int k = ks * 8 + (lane & 3);
            uint32_t a[4][4], b[4][2];
            #pragma unroll
            for (int mt = 0; mt < 4; mt++) {
                const int m = wm * 64 + mt * 16 + (lane >> 2);
                a[mt][0] = __float_as_uint(Abase[m * SROW + k]);
                a[mt][1] = __float_as_uint(Abase[(m + 8) * SROW + k]);
                a[mt][2] = __float_as_uint(Abase[m * SROW + k + 4]);
                a[mt][3] = __float_as_uint(Abase[(m + 8) * SROW + k + 4]);
            }
            #pragma unroll
            for (int nt = 0; nt < 4; nt++) {
                const int n = wn * 32 + nt * 8 + (lane >> 2);
                b[nt][0] = __float_as_uint(Bbase[n * SROW + k]);
                b[nt][1] = __float_as_uint(Bbase[n * SROW + k + 4]);
            }
            #pragma unroll
            for (int mt = 0; mt < 4; mt++)
                #pragma unroll
                for (int nt = 0; nt < 4; nt++)
                    mma_tf32(acc[mt][nt], a[mt], b[nt]);
        }
        __syncthreads();
        if (c + 2 < NC) load_chunk(c + 2, c & 1);
        cpa_commit();
    }

    #pragma unroll
    for (int mt = 0; mt < 4; mt++) {
        const int m = m0 + wm * 64 + mt * 16 + (lane >> 2);
        #pragma unroll
        for (int nt = 0; nt < 4; nt++) {
            const int n = n0 + wn * 32 + nt * 8 + 2 * (lane & 3);
            if (MODE == 0) {
                const int z = blockIdx.z;
                float* outb = (z == 0 ? g_q : (z == 1 ? g_k : g_v));
                const int h = n >> 6, d = n & 63;
                #pragma unroll
                for (int half = 0; half < 2; half++) {
                    const int mm = m + half * 8;
                    const int bb = mm >> 11, t = mm & 2047;
                    float2 o2 = make_float2(rntf32(acc[mt][nt][half * 2]),
                                            rntf32(acc[mt][nt][half * 2 + 1]));
                    *(float2*)(outb + (((size_t)(bb * HH + h) * TT + t) * DD + d)) = o2;
                }
            } else {
                const float2 b2 = *(const float2*)(bias + n);
                #pragma unroll
                for (int half = 0; half < 2; half++) {
                    const int mm = m + half * 8;
                    float2 o2 = make_float2(acc[mt][nt][half * 2] + b2.x,
                                            acc[mt][nt][half * 2 + 1] + b2.y);
                    *(float2*)(out + (size_t)mm * CC + n) = o2;
                }
            }
        }
    }
}

// ---------------------------------------------------------------------------
// Tensor-core causal flash attention (tf32 mma.sync, fp32 softmax).
// Block = 256 thr / 8 warps; q-tile 128 (warp w owns rows w*16..w*16+15);
// k-tile 64; Q fragments register-resident; K/V double-buffered cp.async;
// P round-trips through smem (pad 68 -> conflict-free A-frag reads).
// grid (T/128 [reversed], H, B).
// ---------------------------------------------------------------------------
#define KSS 68    // K smem row stride (floats)
#define VSS 72    // V smem row stride
#define PSS 68    // P/Q-stage smem row stride
#define ATTN_SMEM ((128*PSS + 2*64*KSS + 2*64*VSS) * 4)   // 106496 B

__global__ __launch_bounds__(256) void attn_mma()
{
    extern __shared__ __align__(16) float smf[];
    float* Ps = smf;                         // [128][PSS] (also Q staging)
    float* Ks = smf + 128 * PSS;             // [2][64][KSS]
    float* Vs = Ks + 2 * 64 * KSS;           // [2][64][VSS]
    const uint32_t ks_b = smem_u32(Ks);
    const uint32_t vs_b = smem_u32(Vs);

    const int qt = (gridDim.x - 1) - blockIdx.x;   // heavy tiles first
    const int h = blockIdx.y, b = blockIdx.z;
    const int tid = threadIdx.x, lane = tid & 31, w = tid >> 5;
    const int lr = lane >> 2, la = lane & 3;
    const int q0 = qt * 128;
    const size_t bh = (size_t)(b * HH + h);
    const float* qg = g_q + (bh * TT + q0) * DD;
    const float* kg = g_k + bh * TT * DD;
    const float* vg = g_v + bh * TT * DD;

    auto load_tile = [&](int kt, int buf) {
        const float* ksrc = kg + (size_t)kt * 64 * DD;
        const float* vsrc = vg + (size_t)kt * 64 * DD;
        #pragma unroll
        for (int i = 0; i < 4; i++) {
            int idx = tid + i * 256;
            int row = idx >> 4, seg = idx & 15;
            cpa16(ks_b + (uint32_t)((buf * 64 + row) * KSS + seg * 4) * 4,
                  ksrc + (size_t)row * DD + seg * 4);
            cpa16(vs_b + (uint32_t)((buf * 64 + row) * VSS + seg * 4) * 4,
                  vsrc + (size_t)row * DD + seg * 4);
        }
        cpa_commit();
    };

    load_tile(0, 0);   // overlap with Q staging

    // stage Q (coalesced) then pull fragments to registers, scaled by C^-0.5
    #pragma unroll
    for (int i = 0; i < 8; i++) {
        int idx = tid + i * 256;
        int row = idx >> 4, seg = idx & 15;
        *(float4*)&Ps[row * PSS + seg * 4] =
            *(const float4*)&qg[(size_t)row * DD + seg * 4];
    }
    __syncthreads();
    uint32_t qa[8][4];
    const int mrow = w * 16 + lr;
    #pragma unroll
    for (int ks = 0; ks < 8; ks++) {
        const int k = ks * 8 + la;
        // g_q already tf32; *2^-5 is exact -> still tf32
        qa[ks][0] = __float_as_uint(Ps[mrow * PSS + k] * 0.03125f);
        qa[ks][1] = __float_as_uint(Ps[(mrow + 8) * PSS + k] * 0.03125f);
        qa[ks][2] = __float_as_uint(Ps[mrow * PSS + k + 4] * 0.03125f);
        qa[ks][3] = __float_as_uint(Ps[(mrow + 8) * PSS + k + 4] * 0.03125f);
    }

    float m0 = -1e30f, m1 = -1e30f, l0 = 0.f, l1 = 0.f;
    float oacc[8][4] = {};

    const int nk = 2 * qt + 2;
    const int row0 = q0 + w * 16 + lr;       // global q row (half 0)
    const int row1 = row0 + 8;

    for (int kt = 0; kt < nk; kt++) {
        cpa_wait0();
        __syncthreads();                      // tile kt ready; prev tile fully consumed
        if (kt + 1 < nk) load_tile(kt + 1, (kt + 1) & 1);

        const float* Kb = Ks + (kt & 1) * 64 * KSS;
        const float* Vb = Vs + (kt & 1) * 64 * VSS;

        // ---- S = Q K^T (warp: 16 x 64) ----
        float sacc[8][4] = {};
        #pragma unroll
        for (int ks = 0; ks < 8; ks++) {
            const int k = ks * 8 + la;
            #pragma unroll
            for (int nf = 0; nf < 8; nf++) {
                uint32_t bfr[2];
                bfr[0] = __float_as_uint(Kb[(nf * 8 + lr) * KSS + k]);
                bfr[1] = __float_as_uint(Kb[(nf * 8 + lr) * KSS + k + 4]);
                mma_tf32(sacc[nf], qa[ks], bfr);
            }
        }

        // ---- causal mask (near-diagonal tiles only) ----
        const int s_base = kt * 64;
        if (s_base + 63 > q0 + w * 16) {
            #pragma unroll
            for (int nf = 0; nf < 8; nf++) {
                const int s = s_base + nf * 8 + 2 * la;
                if (s > row0)     sacc[nf][0] = -1e30f;
                if (s + 1 > row0) sacc[nf][1] = -1e30f;
                if (s > row1)     sacc[nf][2] = -1e30f;
                if (s + 1 > row1) sacc[nf][3] = -1e30f;
            }
        }

        // ---- online softmax (two row-halves per thread, quad-reduced) ----
        float mx0 = -1e30f, mx1 = -1e30f;
        #pragma unroll
        for (int nf = 0; nf < 8; nf++) {
            mx0 = fmaxf(mx0, fmaxf(sacc[nf][0], sacc[nf][1]));
            mx1 = fmaxf(mx1, fmaxf(sacc[nf][2], sacc[nf][3]));
        }
        mx0 = fmaxf(mx0, __shfl_xor_sync(0xffffffffu, mx0, 1));
        mx0 = fmaxf(mx0, __shfl_xor_sync(0xffffffffu, mx0, 2));
        mx1 = fmaxf(mx1, __shfl_xor_sync(0xffffffffu, mx1, 1));
        mx1 = fmaxf(mx1, __shfl_xor_sync(0xffffffffu, mx1, 2));
        const float mn0 = fmaxf(m0, mx0), mn1 = fmaxf(m1, mx1);
        const float c0 = __expf(m0 - mn0), c1 = __expf(m1 - mn1);
        float s0 = 0.f, s1 = 0.f;
        #pragma unroll
        for (int nf = 0; nf < 8; nf++) {
            float p0 = __expf(sacc[nf][0] - mn0);
            float p1 = __expf(sacc[nf][1] - mn0);
            float p2 = __expf(sacc[nf][2] - mn1);
            float p3 = __expf(sacc[nf][3] - mn1);
            s0 += p0 + p1; s1 += p2 + p3;
            *(float2*)&Ps[(w * 16 + lr) * PSS + nf * 8 + 2 * la] =
                make_float2(rntf32(p0), rntf32(p1));
            *(float2*)&Ps[(w * 16 + lr + 8) * PSS + nf * 8 + 2 * la] =
                make_float2(rntf32(p2), rntf32(p3));
        }
        s0 += __shfl_xor_sync(0xffffffffu, s0, 1);
        s0 += __shfl_xor_sync(0xffffffffu, s0, 2);
        s1 += __shfl_xor_sync(0xffffffffu, s1, 1);
        s1 += __shfl_xor_sync(0xffffffffu, s1, 2);
        l0 = l0 * c0 + s0;  l1 = l1 * c1 + s1;
        m0 = mn0;           m1 = mn1;
        #pragma unroll
        for (int nf = 0; nf < 8; nf++) {
            oacc[nf][0] *= c0; oacc[nf][1] *= c0;
            oacc[nf][2] *= c1; oacc[nf][3] *= c1;
        }
        __syncwarp();    // P stores visible to PV reads within the warp

        // ---- O += P V ----
        #pragma unroll
        for (int ks = 0; ks < 8; ks++) {
            uint32_t pa[4];
            pa[0] = __float_as_uint(Ps[(w * 16 + lr) * PSS + ks * 8 + la]);
            pa[1] = __float_as_uint(Ps[(w * 16 + lr + 8) * PSS + ks * 8 + la]);
            pa[2] = __float_as_uint(Ps[(w * 16 + lr) * PSS + ks * 8 + la + 4]);
            pa[3] = __float_as_uint(Ps[(w * 16 + lr + 8) * PSS + ks * 8 + la + 4]);
            #pragma unroll
            for (int nf = 0; nf < 8; nf++) {
                uint32_t bfr[2];
                bfr[0] = __float_as_uint(Vb[(ks * 8 + la) * VSS + nf * 8 + lr]);
                bfr[1] = __float_as_uint(Vb[(ks * 8 + la + 4) * VSS + nf * 8 + lr]);
                mma_tf32(oacc[nf], pa, bfr);
            }
        }
    }

    // ---- normalize, write concat layout (tf32-rounded for proj GEMM) ----
    const float inv0 = 1.0f / l0, inv1 = 1.0f / l1;
    #pragma unroll
    for (int nf = 0; nf < 8; nf++) {
        const int d = h * 64 + nf * 8 + 2 * la;
        *(float2*)&g_y[(size_t)(b * TT + row0) * CC + d] =
            make_float2(rntf32(oacc[nf][0] * inv0), rntf32(oacc[nf][1] * inv0));
        *(float2*)&g_y[(size_t)(b * TT + row1) * CC + d] =
            make_float2(rntf32(oacc[nf][2] * inv1), rntf32(oacc[nf][3] * inv1));
    }
}

// ---------------------------------------------------------------------------
extern "C" void kernel_launch(void* const* d_in, const int* in_sizes, int n_in,
                              void* d_out, int out_size)
{
    (void)in_sizes; (void)n_in; (void)out_size;
    const float* x  = (const float*)d_in[0];
    const float* Wq = (const float*)d_in[1];
    const float* Wk = (const float*)d_in[2];
    const float* Wv = (const float*)d_in[3];
    const float* Wp = (const float*)d_in[4];
    const float* bp = (const float*)d_in[5];
    float* out = (float*)d_out;

    cudaFuncSetAttribute(attn_mma,
                         cudaFuncAttributeMaxDynamicSharedMemorySize, ATTN_SMEM);
    cudaFuncSetAttribute(gemm_kernel<0>,
                         cudaFuncAttributeMaxDynamicSharedMemorySize, GEMM_SMEM);
    cudaFuncSetAttribute(gemm_kernel<1>,
                         cudaFuncAttributeMaxDynamicSharedMemorySize, GEMM_SMEM);

    round_kernel<<<(BT * CC / 4 + 255) / 256, 256>>>(x, 0, BT * CC / 4);
    round_kernel<<<(CC * CC / 4 + 255) / 256, 256>>>(Wp, 1, CC * CC / 4);
    transpose_w<<<dim3(32, 2, 48), dim3(32, 8)>>>(Wq, Wk, Wv);

    gemm_kernel<0><<<dim3(BT / 128, CC / 128, 3), 256, GEMM_SMEM>>>(nullptr, nullptr);

    attn_mma<<<dim3(TT / 128, HH, BB), 256, ATTN_SMEM>>>();

    gemm_kernel<1><<<dim3(BT / 128, CC / 128, 1), 256, GEMM_SMEM>>>(bp, out);
}